// round 15
// baseline (speedup 1.0000x reference)
#include <cuda_runtime.h>
#include <cuda_fp16.h>
#include <cstdint>

// ===========================================================================
// Fused LSTM cell, mma.sync. 512-thread CTAs, 2 CTAs/SM -> 32 warps/SM.
// Warp grid 4(M) x 4(N): warp owns 16 rows x 8 gate-cols of ONE chunk of the
// active pair (acc = 16 regs -> fits 64-reg/warp budget at double occupancy;
// total CTA ldsm work unchanged). Weight movement via cp.async.bulk +
// mbarrier (pre-swizzled gmem image). c_ prefetched before MMA; epilogue
// overlaps next pair's bulk flight. f-gate sigmoid in f32 for rel_err margin.
// d_out = [c | h | y], each B*128 fp32.
// ===========================================================================

#define MBAR_OFF  0
#define AS_OFF    128
#define BS_OFF(i) (AS_OFF + 32768 + (i) * 32768)
#define HT_OFF    (AS_OFF + 98304)
#define SMEM_TOT  (HT_OFF + 16384)          // 114816

__device__ __half g_W16r[512 * 256];    // PRE-SWIZZLED gate weights (8 x 32KB chunks)
__device__ __half g_wout16[128 * 128];  // PRE-SWIZZLED w_out (32KB)

// --------------------------------------------------------------------------
// K0: build swizzled gmem images (unchanged from R12/R14).
// --------------------------------------------------------------------------
__device__ __forceinline__ uint4 pack8f(const float* p) {
    float4 v0 = ((const float4*)p)[0], v1 = ((const float4*)p)[1];
    __half2 h0 = __floats2half2_rn(v0.x, v0.y), h1 = __floats2half2_rn(v0.z, v0.w);
    __half2 h2 = __floats2half2_rn(v1.x, v1.y), h3 = __floats2half2_rn(v1.z, v1.w);
    uint4 r;
    r.x = *(uint32_t*)&h0; r.y = *(uint32_t*)&h1;
    r.z = *(uint32_t*)&h2; r.w = *(uint32_t*)&h3;
    return r;
}

__global__ void prep_weights(const float* __restrict__ w,  const float* __restrict__ wi,
                             const float* __restrict__ wf, const float* __restrict__ wo,
                             const float* __restrict__ w_out)
{
    const int stride = gridDim.x * blockDim.x;
    for (int idx = blockIdx.x * blockDim.x + threadIdx.x; idx < 16384; idx += stride) {
        int c = idx >> 11, loc = idx & 2047;
        int r = loc >> 5, ss = loc & 31;
        int seg = ss ^ (r & 7);                    // un-swizzled K segment
        int grp = r >> 5, gate = (r >> 3) & 3, sub = r & 7;
        int gc = c * 16 + grp * 8 + sub;
        const float* src = (gate == 0) ? w : (gate == 1) ? wi : (gate == 2) ? wf : wo;
        ((uint4*)g_W16r)[idx] = pack8f(src + gc * 256 + seg * 8);
    }
    for (int idx = blockIdx.x * blockDim.x + threadIdx.x; idx < 2048; idx += stride) {
        int r = idx >> 4, ss = idx & 15;
        int seg = ss ^ (r & 7);
        ((uint4*)g_wout16)[idx] = pack8f(w_out + r * 128 + seg * 8);
    }
}

// --------------------------------------------------------------------------
// helpers
// --------------------------------------------------------------------------
__device__ __forceinline__ void ldsm_x4(uint32_t addr, uint32_t& r0, uint32_t& r1,
                                        uint32_t& r2, uint32_t& r3)
{
    asm volatile("ldmatrix.sync.aligned.m8n8.x4.shared.b16 {%0,%1,%2,%3}, [%4];"
                 : "=r"(r0), "=r"(r1), "=r"(r2), "=r"(r3) : "r"(addr));
}
__device__ __forceinline__ void mma16816(float* c, const uint32_t* a, uint32_t b0, uint32_t b1)
{
    asm volatile(
        "mma.sync.aligned.m16n8k16.row.col.f32.f16.f16.f32 "
        "{%0,%1,%2,%3},{%4,%5,%6,%7},{%8,%9},{%0,%1,%2,%3};"
        : "+f"(c[0]), "+f"(c[1]), "+f"(c[2]), "+f"(c[3])
        : "r"(a[0]), "r"(a[1]), "r"(a[2]), "r"(a[3]), "r"(b0), "r"(b1));
}
__device__ __forceinline__ void mbar_init(uint32_t a, uint32_t cnt) {
    asm volatile("mbarrier.init.shared.b64 [%0], %1;" :: "r"(a), "r"(cnt) : "memory");
}
__device__ __forceinline__ void mbar_expect_tx(uint32_t a, uint32_t bytes) {
    asm volatile("mbarrier.arrive.expect_tx.shared.b64 _, [%0], %1;" :: "r"(a), "r"(bytes) : "memory");
}
__device__ __forceinline__ void mbar_wait(uint32_t a, uint32_t parity) {
    asm volatile(
        "{\n\t.reg .pred P;\n\t"
        "WL%=:\n\t"
        "mbarrier.try_wait.parity.acquire.cta.shared::cta.b64 P, [%0], %1, 0x989680;\n\t"
        "@!P bra WL%=;\n\t}" :: "r"(a), "r"(parity) : "memory");
}
__device__ __forceinline__ void bulk_g2s(uint32_t dst, const void* src, uint32_t bytes, uint32_t mbar) {
    asm volatile("cp.async.bulk.shared::cta.global.mbarrier::complete_tx::bytes [%0], [%1], %2, [%3];"
                 :: "r"(dst), "l"(src), "r"(bytes), "r"(mbar) : "memory");
}
__device__ __forceinline__ float tanha(float x) {
    float y; asm("tanh.approx.f32 %0, %1;" : "=f"(y) : "f"(x)); return y;
}
__device__ __forceinline__ float2 tanh2(float a, float b) {
    __half2 u = __floats2half2_rn(a, b);
    uint32_t uin = *(uint32_t*)&u, r;
    asm("tanh.approx.f16x2 %0, %1;" : "=r"(r) : "r"(uin));
    __half2 t = *(__half2*)&r;
    return make_float2(__half2float(t.x), __half2float(t.y));
}
__device__ __forceinline__ float2 sig2(float a, float b) {
    float2 t = tanh2(0.5f * a, 0.5f * b);
    return make_float2(fmaf(t.x, 0.5f, 0.5f), fmaf(t.y, 0.5f, 0.5f));
}
__device__ __forceinline__ float sigf(float x) {        // f32 sigmoid (margin)
    return fmaf(tanha(0.5f * x), 0.5f, 0.5f);
}
__device__ __forceinline__ uint32_t swz512(int r, int seg) {   // 512B rows, seg=16B
    return (uint32_t)(r * 512 + ((seg ^ (r & 7)) << 4));
}
__device__ __forceinline__ uint32_t swz256(int r, int seg) {   // 256B rows
    return (uint32_t)(r * 256 + ((seg ^ (r & 7)) << 4));
}

extern __shared__ char smem[];

// --------------------------------------------------------------------------
// Fused kernel. 512 threads = 16 warps in 4(M) x 4(N).
// warpM = warp>>2 (16-row M tile), warpN = warp&3;
// wbuf = warpN>>1 selects the pair-chunk buffer, wh = warpN&1 the 8-col half.
// --------------------------------------------------------------------------
__global__ __launch_bounds__(512, 2) void lstm_fused(
    const float* __restrict__ x, const float* __restrict__ h_,
    const float* __restrict__ c_,
    const float* __restrict__ bz, const float* __restrict__ bi,
    const float* __restrict__ bf, const float* __restrict__ bo,
    const float* __restrict__ bout,
    float* __restrict__ outC, float* __restrict__ outH, float* __restrict__ outY)
{
    const int tid  = threadIdx.x, lane = tid & 31;
    const int warp = tid >> 5;
    const int warpM = warp >> 2, warpN = warp & 3;
    const int wbuf  = warpN >> 1, wh = warpN & 1;
    const int row0 = blockIdx.x * 64;

    const uint32_t sbase = (uint32_t)__cvta_generic_to_shared(smem);
    const uint32_t mb = sbase + MBAR_OFF;

    if (tid == 0) mbar_init(mb, 1);
    __syncthreads();                               // mbar visible to all

    // ---- issue pair 0 bulk copy (DMA engine) ----
    if (tid == 0) {
        mbar_expect_tx(mb, 65536);
        bulk_g2s(sbase + BS_OFF(0), (const char*)g_W16r,         32768, mb);
        bulk_g2s(sbase + BS_OFF(1), (const char*)g_W16r + 32768, 32768, mb);
    }

    // ---- As: xh fp32 -> fp16 (cols 0-127 = x, 128-255 = h_) ----
    for (int i = tid; i < 2048; i += 512) {
        int r = i >> 5, seg = i & 31;
        const float* src = (seg < 16) ? (x  + (size_t)(row0 + r) * 128 + seg * 8)
                                      : (h_ + (size_t)(row0 + r) * 128 + (seg - 16) * 8);
        uint4 pk = pack8f(src);
        *(uint4*)(smem + AS_OFF + swz512(r, seg)) = pk;
    }
    __syncthreads();                               // As visible

    // lane address components
    const int a_lrow = lane & 15;
    const int a_segk = lane >> 4;
    const int b_nloc = ((lane >> 4) & 1) * 8 + (lane & 7);
    const int b_segk = (lane >> 3) & 1;
    const int colq   = wh * 8 + 2 * (lane & 3);    // col within chunk's 16
    const int rq     = lane >> 2;

    float acc[4][4];                               // [gate][ri]

    // ============= 4 iterations of chunk PAIRS =============
    #pragma unroll
    for (int j = 0; j < 4; j++) {
        mbar_wait(mb, j & 1);                      // pair j data ready (acquire)

        const int cc   = j * 2 + wbuf;             // this warp's chunk
        const int colb = cc * 16 + colq;

        // ---- prefetch c_ (consumed ~2500 cyc later) ----
        float2 cpre[2];                            // [rh]
        #pragma unroll
        for (int rh = 0; rh < 2; rh++)
            cpre[rh] = __ldcs((const float2*)(
                c_ + (size_t)(row0 + warpM * 16 + rq + rh * 8) * 128 + colb));

        #pragma unroll
        for (int g = 0; g < 4; g++)
            #pragma unroll
            for (int r = 0; r < 4; r++) acc[g][r] = 0.f;

        // ---- MMA: warp covers 16 rows x 8 cols x 4 gates of its chunk ----
        const uint32_t as0 = sbase + AS_OFF;
        const uint32_t bsW = sbase + BS_OFF(wbuf);
        #pragma unroll
        for (int ks = 0; ks < 16; ks++) {
            uint32_t a[4];
            ldsm_x4(as0 + swz512(warpM * 16 + a_lrow, ks * 2 + a_segk),
                    a[0], a[1], a[2], a[3]);
            uint32_t bb[2][4];                     // gp0: z,i   gp1: f,o
            #pragma unroll
            for (int gp = 0; gp < 2; gp++)
                ldsm_x4(bsW + swz512(wh * 32 + gp * 16 + b_nloc, ks * 2 + b_segk),
                        bb[gp][0], bb[gp][1], bb[gp][2], bb[gp][3]);
            #pragma unroll
            for (int g = 0; g < 4; g++) {
                const int gp = g >> 1, hi = g & 1;
                mma16816(acc[g], a, bb[gp][hi * 2], bb[gp][hi * 2 + 1]);
            }
        }

        __syncthreads();                           // all warps done reading Bs0/Bs1

        // ---- issue next loads (flight covered by epilogue) ----
        if (tid == 0) {
            if (j < 3) {
                mbar_expect_tx(mb, 65536);
                bulk_g2s(sbase + BS_OFF(0),
                         (const char*)g_W16r + (size_t)(2 * j + 2) * 32768, 32768, mb);
                bulk_g2s(sbase + BS_OFF(1),
                         (const char*)g_W16r + (size_t)(2 * j + 3) * 32768, 32768, mb);
            } else {
                mbar_expect_tx(mb, 32768);
                bulk_g2s(sbase + BS_OFF(0), (const char*)g_wout16, 32768, mb);
            }
        }

        // ---- epilogue of chunk cc (f-gate sigmoid in f32 for precision) ----
        {
            const float2 vz = __ldg((const float2*)(bz + colb));
            const float2 vi = __ldg((const float2*)(bi + colb));
            const float2 vf = __ldg((const float2*)(bf + colb));
            const float2 vo = __ldg((const float2*)(bo + colb));
            const int hseg = cc * 2 + wh;
            #pragma unroll
            for (int rh = 0; rh < 2; rh++) {
                const int rloc = warpM * 16 + rq + rh * 8;
                const int row  = row0 + rloc;
                const float2 cold = cpre[rh];
                float2 z  = tanh2(acc[0][rh*2+0] + vz.x, acc[0][rh*2+1] + vz.y);
                float2 si = sig2 (acc[1][rh*2+0] + vi.x, acc[1][rh*2+1] + vi.y);
                float  sf0 = sigf(acc[2][rh*2+0] + vf.x);
                float  sf1 = sigf(acc[2][rh*2+1] + vf.y);
                float2 so = sig2 (acc[3][rh*2+0] + vo.x, acc[3][rh*2+1] + vo.y);
                float c0 = fmaf(sf0, cold.x, si.x * z.x);
                float c1 = fmaf(sf1, cold.y, si.y * z.y);
                float h0 = so.x * tanha(c0);
                float h1 = so.y * tanha(c1);
                __stcs((float2*)(outC + (size_t)row * 128 + colb), make_float2(c0, c1));
                __stcs((float2*)(outH + (size_t)row * 128 + colb), make_float2(h0, h1));
                *(__half2*)(smem + HT_OFF + swz256(rloc, hseg) + (colb & 7) * 2) =
                    __floats2half2_rn(h0, h1);
            }
        }
    }

    mbar_wait(mb, 0);                              // w_out arrived (phase 4)
    __syncthreads();                               // htile visible

    // =================== GEMM2: y = sigmoid(h @ w_out^T + b_out) ==========
    // warp tile: 16 rows x 32 cols.
    float acc2[4][4];
    #pragma unroll
    for (int g = 0; g < 4; g++)
        #pragma unroll
        for (int r = 0; r < 4; r++) acc2[g][r] = 0.f;

    const uint32_t ht0 = sbase + HT_OFF;
    const uint32_t wo0 = sbase + BS_OFF(0);
    #pragma unroll
    for (int ks = 0; ks < 8; ks++) {
        uint32_t a[4];
        ldsm_x4(ht0 + swz256(warpM * 16 + a_lrow, ks * 2 + a_segk),
                a[0], a[1], a[2], a[3]);
        uint32_t bb[2][4];
        #pragma unroll
        for (int gp = 0; gp < 2; gp++)
            ldsm_x4(wo0 + swz256(warpN * 32 + gp * 16 + b_nloc, ks * 2 + b_segk),
                    bb[gp][0], bb[gp][1], bb[gp][2], bb[gp][3]);
        #pragma unroll
        for (int g = 0; g < 4; g++) {
            const int gp = g >> 1, hi = g & 1;
            mma16816(acc2[g], a, bb[gp][hi * 2], bb[gp][hi * 2 + 1]);
        }
    }

    #pragma unroll
    for (int g = 0; g < 4; g++) {
        const int col = warpN * 32 + g * 8 + 2 * (lane & 3);
        const float2 vb = __ldg((const float2*)(bout + col));
        #pragma unroll
        for (int rh = 0; rh < 2; rh++) {
            const int row = row0 + warpM * 16 + rq + rh * 8;
            float2 v = sig2(acc2[g][rh * 2 + 0] + vb.x,
                            acc2[g][rh * 2 + 1] + vb.y);
            __stcs((float2*)(outY + (size_t)row * 128 + col), v);
        }
    }
}

// --------------------------------------------------------------------------
// Launch
// --------------------------------------------------------------------------
extern "C" void kernel_launch(void* const* d_in, const int* in_sizes, int n_in,
                              void* d_out, int out_size)
{
    const float* c_    = (const float*)d_in[0];
    const float* h_    = (const float*)d_in[1];
    const float* x     = (const float*)d_in[2];
    const float* w     = (const float*)d_in[3];
    const float* wi    = (const float*)d_in[4];
    const float* wf    = (const float*)d_in[5];
    const float* wo    = (const float*)d_in[6];
    const float* w_out = (const float*)d_in[7];
    const float* b     = (const float*)d_in[8];
    const float* bi    = (const float*)d_in[9];
    const float* bf    = (const float*)d_in[10];
    const float* bo    = (const float*)d_in[11];
    const float* b_out = (const float*)d_in[12];

    const int B = in_sizes[0] / 128;
    const size_t BC = (size_t)B * 128;
    float* outC = (float*)d_out;
    float* outH = outC + BC;
    float* outY = outH + BC;

    cudaFuncSetAttribute(lstm_fused, cudaFuncAttributeMaxDynamicSharedMemorySize, SMEM_TOT);

    prep_weights<<<64, 256>>>(w, wi, wf, wo, w_out);
    lstm_fused<<<B / 64, 512, SMEM_TOT>>>(x, h_, c_, b, bi, bf, bo, b_out,
                                          outC, outH, outY);
}

// round 17
// speedup vs baseline: 1.2092x; 1.2092x over previous
#include <cuda_runtime.h>
#include <cuda_fp16.h>
#include <cstdint>

// ===========================================================================
// Fused LSTM cell, mma.sync, 2 CTAs/SM. Warp grid 2(M) x 4(N): warp owns
// 32 rows x 8 gate-cols of ONE chunk of the active pair. Weight movement via
// cp.async.bulk with PER-BUFFER mbarriers: a warp waits only for ITS chunk's
// 32KB, halving exposed copy latency. c_ prefetch hoisted above the wait.
// f-gate sigmoid in f32 (rel_err margin). Pre-swizzled weights in gmem.
// d_out = [c | h | y], each B*128 fp32.
// ===========================================================================

#define MBAR0_OFF 0
#define MBAR1_OFF 8
#define AS_OFF    128
#define BS_OFF(i) (AS_OFF + 32768 + (i) * 32768)
#define HT_OFF    (AS_OFF + 98304)
#define SMEM_TOT  (HT_OFF + 16384)          // 114816

__device__ __half g_W16r[512 * 256];    // PRE-SWIZZLED gate weights (8 x 32KB chunks)
__device__ __half g_wout16[128 * 128];  // PRE-SWIZZLED w_out (32KB)

// --------------------------------------------------------------------------
// K0: build swizzled gmem images.
// Gates chunk c (64 rows x 512B): byte(r, seg16) at r*512+((seg^(r&7))<<4).
// Row r: grp=r>>5, gate=(r>>3)&3, sub=r&7 -> gate-col gc = c*16+grp*8+sub.
// w_out (128 rows x 256B): byte(r, seg16) at r*256+((seg^(r&7))<<4).
// --------------------------------------------------------------------------
__device__ __forceinline__ uint4 pack8f(const float* p) {
    float4 v0 = ((const float4*)p)[0], v1 = ((const float4*)p)[1];
    __half2 h0 = __floats2half2_rn(v0.x, v0.y), h1 = __floats2half2_rn(v0.z, v0.w);
    __half2 h2 = __floats2half2_rn(v1.x, v1.y), h3 = __floats2half2_rn(v1.z, v1.w);
    uint4 r;
    r.x = *(uint32_t*)&h0; r.y = *(uint32_t*)&h1;
    r.z = *(uint32_t*)&h2; r.w = *(uint32_t*)&h3;
    return r;
}

__global__ void prep_weights(const float* __restrict__ w,  const float* __restrict__ wi,
                             const float* __restrict__ wf, const float* __restrict__ wo,
                             const float* __restrict__ w_out)
{
    const int stride = gridDim.x * blockDim.x;
    for (int idx = blockIdx.x * blockDim.x + threadIdx.x; idx < 16384; idx += stride) {
        int c = idx >> 11, loc = idx & 2047;
        int r = loc >> 5, ss = loc & 31;
        int seg = ss ^ (r & 7);                    // un-swizzled K segment
        int grp = r >> 5, gate = (r >> 3) & 3, sub = r & 7;
        int gc = c * 16 + grp * 8 + sub;
        const float* src = (gate == 0) ? w : (gate == 1) ? wi : (gate == 2) ? wf : wo;
        ((uint4*)g_W16r)[idx] = pack8f(src + gc * 256 + seg * 8);
    }
    for (int idx = blockIdx.x * blockDim.x + threadIdx.x; idx < 2048; idx += stride) {
        int r = idx >> 4, ss = idx & 15;
        int seg = ss ^ (r & 7);
        ((uint4*)g_wout16)[idx] = pack8f(w_out + r * 128 + seg * 8);
    }
}

// --------------------------------------------------------------------------
// helpers
// --------------------------------------------------------------------------
__device__ __forceinline__ void ldsm_x4(uint32_t addr, uint32_t& r0, uint32_t& r1,
                                        uint32_t& r2, uint32_t& r3)
{
    asm volatile("ldmatrix.sync.aligned.m8n8.x4.shared.b16 {%0,%1,%2,%3}, [%4];"
                 : "=r"(r0), "=r"(r1), "=r"(r2), "=r"(r3) : "r"(addr));
}
__device__ __forceinline__ void mma16816(float* c, const uint32_t* a, uint32_t b0, uint32_t b1)
{
    asm volatile(
        "mma.sync.aligned.m16n8k16.row.col.f32.f16.f16.f32 "
        "{%0,%1,%2,%3},{%4,%5,%6,%7},{%8,%9},{%0,%1,%2,%3};"
        : "+f"(c[0]), "+f"(c[1]), "+f"(c[2]), "+f"(c[3])
        : "r"(a[0]), "r"(a[1]), "r"(a[2]), "r"(a[3]), "r"(b0), "r"(b1));
}
__device__ __forceinline__ void mbar_init(uint32_t a, uint32_t cnt) {
    asm volatile("mbarrier.init.shared.b64 [%0], %1;" :: "r"(a), "r"(cnt) : "memory");
}
__device__ __forceinline__ void mbar_expect_tx(uint32_t a, uint32_t bytes) {
    asm volatile("mbarrier.arrive.expect_tx.shared.b64 _, [%0], %1;" :: "r"(a), "r"(bytes) : "memory");
}
__device__ __forceinline__ void mbar_wait(uint32_t a, uint32_t parity) {
    asm volatile(
        "{\n\t.reg .pred P;\n\t"
        "WL%=:\n\t"
        "mbarrier.try_wait.parity.acquire.cta.shared::cta.b64 P, [%0], %1, 0x989680;\n\t"
        "@!P bra WL%=;\n\t}" :: "r"(a), "r"(parity) : "memory");
}
__device__ __forceinline__ void bulk_g2s(uint32_t dst, const void* src, uint32_t bytes, uint32_t mbar) {
    asm volatile("cp.async.bulk.shared::cta.global.mbarrier::complete_tx::bytes [%0], [%1], %2, [%3];"
                 :: "r"(dst), "l"(src), "r"(bytes), "r"(mbar) : "memory");
}
__device__ __forceinline__ float tanha(float x) {
    float y; asm("tanh.approx.f32 %0, %1;" : "=f"(y) : "f"(x)); return y;
}
__device__ __forceinline__ float2 tanh2(float a, float b) {
    __half2 u = __floats2half2_rn(a, b);
    uint32_t uin = *(uint32_t*)&u, r;
    asm("tanh.approx.f16x2 %0, %1;" : "=r"(r) : "r"(uin));
    __half2 t = *(__half2*)&r;
    return make_float2(__half2float(t.x), __half2float(t.y));
}
__device__ __forceinline__ float2 sig2(float a, float b) {
    float2 t = tanh2(0.5f * a, 0.5f * b);
    return make_float2(fmaf(t.x, 0.5f, 0.5f), fmaf(t.y, 0.5f, 0.5f));
}
__device__ __forceinline__ float sigf(float x) {        // f32 sigmoid (precision)
    return fmaf(tanha(0.5f * x), 0.5f, 0.5f);
}
__device__ __forceinline__ uint32_t swz512(int r, int seg) {   // 512B rows, seg=16B
    return (uint32_t)(r * 512 + ((seg ^ (r & 7)) << 4));
}
__device__ __forceinline__ uint32_t swz256(int r, int seg) {   // 256B rows
    return (uint32_t)(r * 256 + ((seg ^ (r & 7)) << 4));
}

extern __shared__ char smem[];

// --------------------------------------------------------------------------
// Fused kernel. 256 threads = 8 warps in 2(M) x 4(N).
// warpM = warp>>2 (32-row M tile), warpN = warp&3;
// wbuf = warpN>>1 selects the pair-chunk buffer, wh = warpN&1 the 8-col half.
// --------------------------------------------------------------------------
__global__ __launch_bounds__(256, 2) void lstm_fused(
    const float* __restrict__ x, const float* __restrict__ h_,
    const float* __restrict__ c_,
    const float* __restrict__ bz, const float* __restrict__ bi,
    const float* __restrict__ bf, const float* __restrict__ bo,
    const float* __restrict__ bout,
    float* __restrict__ outC, float* __restrict__ outH, float* __restrict__ outY)
{
    const int tid  = threadIdx.x, lane = tid & 31;
    const int warp = tid >> 5;
    const int warpM = warp >> 2, warpN = warp & 3;
    const int wbuf  = warpN >> 1, wh = warpN & 1;
    const int row0 = blockIdx.x * 64;

    const uint32_t sbase = (uint32_t)__cvta_generic_to_shared(smem);
    const uint32_t mb0 = sbase + MBAR0_OFF, mb1 = sbase + MBAR1_OFF;
    const uint32_t mbW = wbuf ? mb1 : mb0;

    if (tid == 0) { mbar_init(mb0, 1); mbar_init(mb1, 1); }
    __syncthreads();                               // mbars visible to all

    // ---- issue pair 0 bulk copies (per-buffer mbarriers) ----
    if (tid == 0) {
        mbar_expect_tx(mb0, 32768);
        bulk_g2s(sbase + BS_OFF(0), (const char*)g_W16r,         32768, mb0);
        mbar_expect_tx(mb1, 32768);
        bulk_g2s(sbase + BS_OFF(1), (const char*)g_W16r + 32768, 32768, mb1);
    }

    // ---- As: xh fp32 -> fp16 (cols 0-127 = x, 128-255 = h_) ----
    for (int i = tid; i < 2048; i += 256) {
        int r = i >> 5, seg = i & 31;
        const float* src = (seg < 16) ? (x  + (size_t)(row0 + r) * 128 + seg * 8)
                                      : (h_ + (size_t)(row0 + r) * 128 + (seg - 16) * 8);
        uint4 pk = pack8f(src);
        *(uint4*)(smem + AS_OFF + swz512(r, seg)) = pk;
    }
    __syncthreads();                               // As visible

    // lane address components
    const int a_lrow = lane & 15;
    const int a_segk = lane >> 4;
    const int b_nloc = ((lane >> 4) & 1) * 8 + (lane & 7);
    const int b_segk = (lane >> 3) & 1;
    const int colq   = wh * 8 + 2 * (lane & 3);    // col within chunk's 16
    const int rq     = lane >> 2;

    float acc[2][4][4];

    // ============= 4 iterations of chunk PAIRS =============
    #pragma unroll
    for (int j = 0; j < 4; j++) {
        const int cc   = j * 2 + wbuf;             // this warp's chunk
        const int colb = cc * 16 + colq;

        // ---- c_ prefetch BEFORE the wait (flight overlaps copy wait) ----
        float2 cpre[2][2];                         // [mt][rh]
        #pragma unroll
        for (int mt = 0; mt < 2; mt++)
            #pragma unroll
            for (int rh = 0; rh < 2; rh++)
                cpre[mt][rh] = __ldcs((const float2*)(
                    c_ + (size_t)(row0 + warpM * 32 + mt * 16 + rq + rh * 8) * 128 + colb));

        #pragma unroll
        for (int mt = 0; mt < 2; mt++)
            #pragma unroll
            for (int g = 0; g < 4; g++)
                #pragma unroll
                for (int r = 0; r < 4; r++) acc[mt][g][r] = 0.f;

        mbar_wait(mbW, j & 1);                     // wait ONLY this warp's chunk

        // ---- MMA: warp covers 32 rows x 8 cols x 4 gates of its chunk ----
        const uint32_t as0 = sbase + AS_OFF;
        const uint32_t bsW = sbase + BS_OFF(wbuf);
        #pragma unroll
        for (int ks = 0; ks < 16; ks++) {
            uint32_t a[2][4];
            #pragma unroll
            for (int mt = 0; mt < 2; mt++)
                ldsm_x4(as0 + swz512(warpM * 32 + mt * 16 + a_lrow, ks * 2 + a_segk),
                        a[mt][0], a[mt][1], a[mt][2], a[mt][3]);
            uint32_t bb[2][4];                     // gp0: z,i   gp1: f,o
            #pragma unroll
            for (int gp = 0; gp < 2; gp++)
                ldsm_x4(bsW + swz512(wh * 32 + gp * 16 + b_nloc, ks * 2 + b_segk),
                        bb[gp][0], bb[gp][1], bb[gp][2], bb[gp][3]);
            #pragma unroll
            for (int g = 0; g < 4; g++) {
                const int gp = g >> 1, hi = g & 1;
                #pragma unroll
                for (int mt = 0; mt < 2; mt++)
                    mma16816(acc[mt][g], a[mt], bb[gp][hi * 2], bb[gp][hi * 2 + 1]);
            }
        }

        __syncthreads();                           // all warps done reading Bs0/Bs1

        // ---- issue next loads (flight covered by epilogue) ----
        if (tid == 0) {
            if (j < 3) {
                mbar_expect_tx(mb0, 32768);
                bulk_g2s(sbase + BS_OFF(0),
                         (const char*)g_W16r + (size_t)(2 * j + 2) * 32768, 32768, mb0);
                mbar_expect_tx(mb1, 32768);
                bulk_g2s(sbase + BS_OFF(1),
                         (const char*)g_W16r + (size_t)(2 * j + 3) * 32768, 32768, mb1);
            } else {
                mbar_expect_tx(mb0, 32768);
                bulk_g2s(sbase + BS_OFF(0), (const char*)g_wout16, 32768, mb0);
            }
        }

        // ---- epilogue of chunk cc (f-gate sigmoid in f32) ----
        {
            const float2 vz = __ldg((const float2*)(bz + colb));
            const float2 vi = __ldg((const float2*)(bi + colb));
            const float2 vf = __ldg((const float2*)(bf + colb));
            const float2 vo = __ldg((const float2*)(bo + colb));
            const int hseg = cc * 2 + wh;
            #pragma unroll
            for (int mt = 0; mt < 2; mt++) {
                #pragma unroll
                for (int rh = 0; rh < 2; rh++) {
                    const int rloc = warpM * 32 + mt * 16 + rq + rh * 8;
                    const int row  = row0 + rloc;
                    const float2 cold = cpre[mt][rh];
                    float2 z  = tanh2(acc[mt][0][rh*2+0] + vz.x, acc[mt][0][rh*2+1] + vz.y);
                    float2 si = sig2 (acc[mt][1][rh*2+0] + vi.x, acc[mt][1][rh*2+1] + vi.y);
                    float  sf0 = sigf(acc[mt][2][rh*2+0] + vf.x);
                    float  sf1 = sigf(acc[mt][2][rh*2+1] + vf.y);
                    float2 so = sig2 (acc[mt][3][rh*2+0] + vo.x, acc[mt][3][rh*2+1] + vo.y);
                    float c0 = fmaf(sf0, cold.x, si.x * z.x);
                    float c1 = fmaf(sf1, cold.y, si.y * z.y);
                    float h0 = so.x * tanha(c0);
                    float h1 = so.y * tanha(c1);
                    __stcs((float2*)(outC + (size_t)row * 128 + colb), make_float2(c0, c1));
                    __stcs((float2*)(outH + (size_t)row * 128 + colb), make_float2(h0, h1));
                    *(__half2*)(smem + HT_OFF + swz256(rloc, hseg) + (colb & 7) * 2) =
                        __floats2half2_rn(h0, h1);
                }
            }
        }
    }

    mbar_wait(mb0, 0);                             // w_out arrived (mb0 phase 4)
    __syncthreads();                               // htile visible

    // =================== GEMM2: y = sigmoid(h @ w_out^T + b_out) ==========
    // warp tile: 32 rows x 32 cols.
    float acc2[2][4][4];
    #pragma unroll
    for (int mt = 0; mt < 2; mt++)
        #pragma unroll
        for (int g = 0; g < 4; g++)
            #pragma unroll
            for (int r = 0; r < 4; r++) acc2[mt][g][r] = 0.f;

    const uint32_t ht0 = sbase + HT_OFF;
    const uint32_t wo0 = sbase + BS_OFF(0);
    #pragma unroll
    for (int ks = 0; ks < 8; ks++) {
        uint32_t a[2][4];
        #pragma unroll
        for (int mt = 0; mt < 2; mt++)
            ldsm_x4(ht0 + swz256(warpM * 32 + mt * 16 + a_lrow, ks * 2 + a_segk),
                    a[mt][0], a[mt][1], a[mt][2], a[mt][3]);
        uint32_t bb[2][4];
        #pragma unroll
        for (int gp = 0; gp < 2; gp++)
            ldsm_x4(wo0 + swz256(warpN * 32 + gp * 16 + b_nloc, ks * 2 + b_segk),
                    bb[gp][0], bb[gp][1], bb[gp][2], bb[gp][3]);
        #pragma unroll
        for (int g = 0; g < 4; g++) {
            const int gp = g >> 1, hi = g & 1;
            #pragma unroll
            for (int mt = 0; mt < 2; mt++)
                mma16816(acc2[mt][g], a[mt], bb[gp][hi * 2], bb[gp][hi * 2 + 1]);
        }
    }

    #pragma unroll
    for (int g = 0; g < 4; g++) {
        const int col = warpN * 32 + g * 8 + 2 * (lane & 3);
        const float2 vb = __ldg((const float2*)(bout + col));
        #pragma unroll
        for (int mt = 0; mt < 2; mt++) {
            #pragma unroll
            for (int rh = 0; rh < 2; rh++) {
                const int row = row0 + warpM * 32 + mt * 16 + rq + rh * 8;
                float2 v = sig2(acc2[mt][g][rh * 2 + 0] + vb.x,
                                acc2[mt][g][rh * 2 + 1] + vb.y);
                __stcs((float2*)(outY + (size_t)row * 128 + col), v);
            }
        }
    }
}

// --------------------------------------------------------------------------
// Launch
// --------------------------------------------------------------------------
extern "C" void kernel_launch(void* const* d_in, const int* in_sizes, int n_in,
                              void* d_out, int out_size)
{
    const float* c_    = (const float*)d_in[0];
    const float* h_    = (const float*)d_in[1];
    const float* x     = (const float*)d_in[2];
    const float* w     = (const float*)d_in[3];
    const float* wi    = (const float*)d_in[4];
    const float* wf    = (const float*)d_in[5];
    const float* wo    = (const float*)d_in[6];
    const float* w_out = (const float*)d_in[7];
    const float* b     = (const float*)d_in[8];
    const float* bi    = (const float*)d_in[9];
    const float* bf    = (const float*)d_in[10];
    const float* bo    = (const float*)d_in[11];
    const float* b_out = (const float*)d_in[12];

    const int B = in_sizes[0] / 128;
    const size_t BC = (size_t)B * 128;
    float* outC = (float*)d_out;
    float* outH = outC + BC;
    float* outY = outH + BC;

    cudaFuncSetAttribute(lstm_fused, cudaFuncAttributeMaxDynamicSharedMemorySize, SMEM_TOT);

    prep_weights<<<64, 256>>>(w, wi, wf, wo, w_out);
    lstm_fused<<<B / 64, 256, SMEM_TOT>>>(x, h_, c_, b, bi, bf, bo, b_out,
                                          outC, outH, outY);
}